// round 16
// baseline (speedup 1.0000x reference)
#include <cuda_runtime.h>
#include <math.h>

#define D_MODEL 2048
#define NUM_HEADS 16
#define HEAD_DIM 128
#define MAX_SEQ_LEN 32768
#define KB 64                       // key-blocks per head (splits per head)
#define CHUNK (MAX_SEQ_LEN / KB)    // 512 keys per block
#define HALF (CHUNK / 2)            // 256 keys per stream
#define SCALE 0.08838834764831845f  // 1/sqrt(128)

// ---------------- device scratch (no allocations allowed) ----------------
__device__ float g_q[D_MODEL];
__device__ float g_k[D_MODEL];
__device__ float g_v[D_MODEL];
__device__ float g_pm[NUM_HEADS * KB];
__device__ float g_pl[NUM_HEADS * KB];
__device__ float g_pacc[NUM_HEADS * KB * HEAD_DIM];

// ---------------- K1: single-wave persistent QKV matvecs -------------------
// 512 blocks x 256 threads (<= resident capacity at ~60 regs => ONE wave,
// no wave-transition ramps). Each block computes 12 rows in 3 iterations of
// 4 rows; per iteration each thread front-batches its 8 weight float4 loads.
__global__ __launch_bounds__(256) void qkv_kernel(const float* __restrict__ x,
                                                  const float* __restrict__ Wq,
                                                  const float* __restrict__ Wk,
                                                  const float* __restrict__ Wv,
                                                  float* __restrict__ y) {
    __shared__ float xs[D_MODEL];
    __shared__ float part[8];
    int tid  = threadIdx.x;
    int sub  = tid & 63;
    int lane = tid & 31;
    int rg   = tid >> 6;                      // row-group 0..3 within block

    // prefetch iteration-0 weights before the x chain (hides x latency)
    int grow0 = blockIdx.x * 12 + rg;         // rows r*4+rg, r=0
    const float* W0 = (grow0 >> 11) == 0 ? Wq : ((grow0 >> 11) == 1 ? Wk : Wv);
    const float4* wr0 = (const float4*)(W0 + (size_t)(grow0 & 2047) * D_MODEL);
    float4 w[8];
#pragma unroll
    for (int it = 0; it < 8; it++) w[it] = __ldcs(wr0 + sub + it * 64);

    {
        float4* xs4 = (float4*)xs;
        const float4* x4 = (const float4*)x;
#pragma unroll
        for (int i = 0; i < 2; i++) xs4[tid + i * 256] = x4[tid + i * 256];
    }
    if (blockIdx.x == 0) {
#pragma unroll
        for (int i = 0; i < 8; i++) y[tid + i * 256] = 0.f;   // zero y
    }
    __syncthreads();

#pragma unroll
    for (int r = 0; r < 3; r++) {
        int grow = blockIdx.x * 12 + r * 4 + rg;   // 0..6143
        int mat  = grow >> 11;                     // 0=Wq 1=Wk 2=Wv
        int row  = grow & 2047;

        float acc = 0.f;
#pragma unroll
        for (int it = 0; it < 8; it++) {
            int j = sub + it * 64;
            acc += xs[j * 4 + 0] * w[it].x + xs[j * 4 + 1] * w[it].y
                 + xs[j * 4 + 2] * w[it].z + xs[j * 4 + 3] * w[it].w;
        }

        // prefetch next iteration's weights while the reduce drains
        if (r < 2) {
            int gn = blockIdx.x * 12 + (r + 1) * 4 + rg;
            const float* Wn = (gn >> 11) == 0 ? Wq : ((gn >> 11) == 1 ? Wk : Wv);
            const float4* wrn = (const float4*)(Wn + (size_t)(gn & 2047) * D_MODEL);
#pragma unroll
            for (int it = 0; it < 8; it++) w[it] = __ldcs(wrn + sub + it * 64);
        }

#pragma unroll
        for (int o = 16; o; o >>= 1) acc += __shfl_xor_sync(0xffffffffu, acc, o);
        if (lane == 0) part[tid >> 5] = acc;
        __syncthreads();
        if (sub == 0) {
            float* dst = (mat == 0) ? g_q : ((mat == 1) ? g_k : g_v);
            int p = (tid >> 5);
            dst[row] = part[p] + part[p + 1];
        }
        __syncthreads();
    }
}

// ---------------- K2: FUSED cache copy + split flash attention (R12) ------
// grid = NUM_HEADS * KB = 1024 blocks of 256 threads.
__global__ __launch_bounds__(256) void fused_copy_attn_kernel(
        const float4* __restrict__ pk,
        const float4* __restrict__ pv,
        float4* __restrict__ ok,
        float4* __restrict__ ov,
        const int* __restrict__ ci_p) {
    int h  = blockIdx.x / KB;
    int kb = blockIdx.x % KB;
    int ci = *ci_p;
    int kstart = kb * CHUNK;

    __shared__ float wm[8], wl[8];
    __shared__ float wacc[8][HEAD_DIM];

    int tid = threadIdx.x, wid = tid >> 5, lane = tid & 31;

    float4 q     = ((const float4*)(g_q + h * HEAD_DIM))[lane];
    float4 foldk = ((const float4*)(g_k + h * HEAD_DIM))[lane];
    float4 foldv = ((const float4*)(g_v + h * HEAD_DIM))[lane];

    float m = -INFINITY, l = 0.f;
    float4 acc = make_float4(0.f, 0.f, 0.f, 0.f);

    const int seg_stride = NUM_HEADS * (HEAD_DIM / 4);   // 512 float4/key row
    const int hbase = h * (HEAD_DIM / 4) + lane;

    for (int it = 0; it < HALF / 8; it++) {
        int keyA = kstart + wid + it * 8;
        int keyB = keyA + HALF;
        size_t ia = (size_t)keyA * seg_stride + hbase;
        size_t ib = (size_t)keyB * seg_stride + hbase;

        float4 kA, vA, kB, vB;
        if (keyA == ci) { kA = foldk; vA = foldv; }
        else            { kA = __ldcs(pk + ia); vA = __ldcs(pv + ia); }
        if (keyB == ci) { kB = foldk; vB = foldv; }
        else            { kB = __ldcs(pk + ib); vB = __ldcs(pv + ib); }
        __stcs(ok + ia, kA); __stcs(ov + ia, vA);
        __stcs(ok + ib, kB); __stcs(ov + ib, vB);

        bool aval = keyA < ci;
        bool bval = keyB < ci;
        if (aval || bval) {
            float sA = kA.x * q.x + kA.y * q.y + kA.z * q.z + kA.w * q.w;
            float sB = kB.x * q.x + kB.y * q.y + kB.z * q.z + kB.w * q.w;
#pragma unroll
            for (int o = 16; o; o >>= 1) {
                sA += __shfl_xor_sync(0xffffffffu, sA, o);
                sB += __shfl_xor_sync(0xffffffffu, sB, o);
            }
            sA = aval ? sA * SCALE : -INFINITY;
            sB = bval ? sB * SCALE : -INFINITY;
            float mn   = fmaxf(m, fmaxf(sA, sB));
            float corr = __expf(m - mn);
            float pA   = __expf(sA - mn);
            float pB   = __expf(sB - mn);
            acc.x = acc.x * corr + pA * vA.x + pB * vB.x;
            acc.y = acc.y * corr + pA * vA.y + pB * vB.y;
            acc.z = acc.z * corr + pA * vA.z + pB * vB.z;
            acc.w = acc.w * corr + pA * vA.w + pB * vB.w;
            l = l * corr + pA + pB;
            m = mn;
        }
    }

    wacc[wid][lane * 4 + 0] = acc.x;
    wacc[wid][lane * 4 + 1] = acc.y;
    wacc[wid][lane * 4 + 2] = acc.z;
    wacc[wid][lane * 4 + 3] = acc.w;
    if (lane == 0) { wm[wid] = m; wl[wid] = l; }
    __syncthreads();

    if (tid < HEAD_DIM) {
        float mb = -INFINITY;
#pragma unroll
        for (int w = 0; w < 8; w++) mb = fmaxf(mb, wm[w]);
        float lb = 0.f, od = 0.f;
        if (mb != -INFINITY) {
#pragma unroll
            for (int w = 0; w < 8; w++) {
                float e = __expf(wm[w] - mb);
                lb += wl[w] * e;
                od += wacc[w][tid] * e;
            }
        }
        int idx = h * KB + kb;
        g_pacc[idx * HEAD_DIM + tid] = od;
        if (tid == 0) { g_pm[idx] = mb; g_pl[idx] = lb; }
    }
}

// ---------------- K3: per-head reduce + head-sliced projection -------------
// 512 blocks x 256 threads (single wave). Block (h, jg) handles 64 y-rows;
// warp w takes 8 rows, front-batching all 8 Wo float4 loads (one memory
// phase), then one interleaved 8-chain shuffle reduce + 8 atomics.
__global__ __launch_bounds__(256) void proj_head_kernel(
        const float* __restrict__ Wo, float* __restrict__ y) {
    int bid = blockIdx.x;
    int h   = bid >> 5;
    int jg  = bid & 31;
    int tid = threadIdx.x, warp = tid >> 5, lane = tid & 31;

    __shared__ float attn_sh[HEAD_DIM];
    __shared__ float red[HEAD_DIM];

    int rbase = jg * 64 + warp * 8;           // 8 rows per warp
    const float* wbase = Wo + (size_t)h * HEAD_DIM;

    // ---- front-batch ALL 8 rows' weights (128B/thread in flight) ----
    float4 w[8];
#pragma unroll
    for (int u = 0; u < 8; u++)
        w[u] = __ldcs((const float4*)(wbase + (size_t)(rbase + u) * D_MODEL) + lane);

    // ---- replicated per-head split combine (includes new-key term) ----
    if (tid < HEAD_DIM) red[tid] = g_q[h * HEAD_DIM + tid] * g_k[h * HEAD_DIM + tid];
    __syncthreads();
    for (int s = 64; s; s >>= 1) {
        if (tid < s) red[tid] += red[tid + s];
        __syncthreads();
    }
    float s_new = red[0] * SCALE;             // new key always valid

    if (tid < HEAD_DIM) {
        float mg = s_new;
#pragma unroll 8
        for (int sp = 0; sp < KB; sp++) mg = fmaxf(mg, g_pm[h * KB + sp]);
        float en  = __expf(s_new - mg);
        float num = en * g_v[h * HEAD_DIM + tid];
        float den = en;
#pragma unroll 8
        for (int sp = 0; sp < KB; sp++) {
            float e = __expf(g_pm[h * KB + sp] - mg);
            num += e * g_pacc[(h * KB + sp) * HEAD_DIM + tid];
            den += e * g_pl[h * KB + sp];
        }
        attn_sh[tid] = num / den;
    }
    __syncthreads();

    // ---- one reduction phase: 8 interleaved shuffle chains ----
    float4 a = ((const float4*)attn_sh)[lane];
    float s[8];
#pragma unroll
    for (int u = 0; u < 8; u++)
        s[u] = w[u].x * a.x + w[u].y * a.y + w[u].z * a.z + w[u].w * a.w;
#pragma unroll
    for (int o = 16; o; o >>= 1) {
#pragma unroll
        for (int u = 0; u < 8; u++)
            s[u] += __shfl_xor_sync(0xffffffffu, s[u], o);
    }
    if (lane == 0) {
#pragma unroll
        for (int u = 0; u < 8; u++)
            atomicAdd(y + rbase + u, s[u]);
    }
}

// ---------------- launch ---------------------------------------------------
extern "C" void kernel_launch(void* const* d_in, const int* in_sizes, int n_in,
                              void* d_out, int out_size) {
    const float* x  = (const float*)d_in[0];
    const float* Wq = (const float*)d_in[1];
    const float* Wk = (const float*)d_in[2];
    const float* Wv = (const float*)d_in[3];
    const float* Wo = (const float*)d_in[4];
    const float* pk = (const float*)d_in[5];
    const float* pv = (const float*)d_in[6];
    const int*   ci = (const int*)d_in[7];

    float* y  = (float*)d_out;
    float* ok = y + D_MODEL;
    float* ov = ok + (size_t)MAX_SEQ_LEN * D_MODEL;

    qkv_kernel<<<512, 256>>>(x, Wq, Wk, Wv, y);
    fused_copy_attn_kernel<<<NUM_HEADS * KB, 256>>>(
        (const float4*)pk, (const float4*)pv,
        (float4*)ok, (float4*)ov, ci);
    proj_head_kernel<<<NUM_HEADS * 32, 256>>>(Wo, y);
}

// round 17
// speedup vs baseline: 1.0759x; 1.0759x over previous
#include <cuda_runtime.h>
#include <math.h>

#define D_MODEL 2048
#define NUM_HEADS 16
#define HEAD_DIM 128
#define MAX_SEQ_LEN 32768
#define KB 64                       // key-blocks per head (splits per head)
#define CHUNK (MAX_SEQ_LEN / KB)    // 512 keys per block
#define HALF (CHUNK / 2)            // 256 keys per stream
#define SCALE 0.08838834764831845f  // 1/sqrt(128)

// ---------------- device scratch (no allocations allowed) ----------------
__device__ float g_q[D_MODEL];
__device__ float g_k[D_MODEL];
__device__ float g_v[D_MODEL];
__device__ float g_pm[NUM_HEADS * KB];
__device__ float g_pl[NUM_HEADS * KB];
__device__ float g_pacc[NUM_HEADS * KB * HEAD_DIM];

// ---------------- K1: fused QKV matvecs, weights prefetched first (R14) ----
// 6144 rows (Wq|Wk|Wv) * 64 threads = 1536 blocks of 256. Weight LDGs issue
// before the x->smem->barrier chain so the 48MB stream starts at cycle ~0.
__global__ __launch_bounds__(256) void qkv_kernel(const float* __restrict__ x,
                                                  const float* __restrict__ Wq,
                                                  const float* __restrict__ Wk,
                                                  const float* __restrict__ Wv,
                                                  float* __restrict__ y) {
    __shared__ float xs[D_MODEL];
    __shared__ float part[8];
    int tid = threadIdx.x;

    int grow = blockIdx.x * 4 + (tid >> 6);   // 0..6143 global row
    int sub  = tid & 63;
    int lane = tid & 31;
    int mat  = grow >> 11;                    // 0=Wq 1=Wk 2=Wv
    int row  = grow & 2047;
    const float* W = (mat == 0) ? Wq : ((mat == 1) ? Wk : Wv);
    const float4* wr = (const float4*)(W + (size_t)row * D_MODEL);

    // ---- weight loads issued FIRST (independent of x) ----
    float4 w[8];
#pragma unroll
    for (int it = 0; it < 8; it++) w[it] = __ldcs(wr + sub + it * 64);

    // ---- x -> smem chain (hidden under the weight stream) ----
    {
        float4* xs4 = (float4*)xs;
        const float4* x4 = (const float4*)x;
#pragma unroll
        for (int i = 0; i < 2; i++) xs4[tid + i * 256] = x4[tid + i * 256];
    }
    if (blockIdx.x == 0) {
        // zero y (poisoned by harness); proj accumulates into it atomically
#pragma unroll
        for (int i = 0; i < 8; i++) y[tid + i * 256] = 0.f;
    }
    __syncthreads();

    float acc = 0.f;
#pragma unroll
    for (int it = 0; it < 8; it++) {
        int j = sub + it * 64;
        acc += xs[j * 4 + 0] * w[it].x + xs[j * 4 + 1] * w[it].y
             + xs[j * 4 + 2] * w[it].z + xs[j * 4 + 3] * w[it].w;
    }
#pragma unroll
    for (int o = 16; o; o >>= 1) acc += __shfl_xor_sync(0xffffffffu, acc, o);

    if (lane == 0) part[tid >> 5] = acc;
    __syncthreads();
    if (sub == 0) {
        float* dst = (mat == 0) ? g_q : ((mat == 1) ? g_k : g_v);
        int p = (tid >> 5);
        dst[row] = part[p] + part[p + 1];
    }
}

// ---------------- K2: FUSED cache copy + split flash attention (R12) ------
// grid = NUM_HEADS * KB = 1024 blocks of 256 threads.
__global__ __launch_bounds__(256) void fused_copy_attn_kernel(
        const float4* __restrict__ pk,
        const float4* __restrict__ pv,
        float4* __restrict__ ok,
        float4* __restrict__ ov,
        const int* __restrict__ ci_p) {
    int h  = blockIdx.x / KB;
    int kb = blockIdx.x % KB;
    int ci = *ci_p;
    int kstart = kb * CHUNK;

    __shared__ float wm[8], wl[8];
    __shared__ float wacc[8][HEAD_DIM];

    int tid = threadIdx.x, wid = tid >> 5, lane = tid & 31;

    float4 q     = ((const float4*)(g_q + h * HEAD_DIM))[lane];
    float4 foldk = ((const float4*)(g_k + h * HEAD_DIM))[lane];
    float4 foldv = ((const float4*)(g_v + h * HEAD_DIM))[lane];

    float m = -INFINITY, l = 0.f;
    float4 acc = make_float4(0.f, 0.f, 0.f, 0.f);

    const int seg_stride = NUM_HEADS * (HEAD_DIM / 4);   // 512 float4/key row
    const int hbase = h * (HEAD_DIM / 4) + lane;

    for (int it = 0; it < HALF / 8; it++) {
        int keyA = kstart + wid + it * 8;
        int keyB = keyA + HALF;
        size_t ia = (size_t)keyA * seg_stride + hbase;
        size_t ib = (size_t)keyB * seg_stride + hbase;

        float4 kA, vA, kB, vB;
        if (keyA == ci) { kA = foldk; vA = foldv; }
        else            { kA = __ldcs(pk + ia); vA = __ldcs(pv + ia); }
        if (keyB == ci) { kB = foldk; vB = foldv; }
        else            { kB = __ldcs(pk + ib); vB = __ldcs(pv + ib); }
        __stcs(ok + ia, kA); __stcs(ov + ia, vA);
        __stcs(ok + ib, kB); __stcs(ov + ib, vB);

        bool aval = keyA < ci;
        bool bval = keyB < ci;
        if (aval || bval) {
            float sA = kA.x * q.x + kA.y * q.y + kA.z * q.z + kA.w * q.w;
            float sB = kB.x * q.x + kB.y * q.y + kB.z * q.z + kB.w * q.w;
#pragma unroll
            for (int o = 16; o; o >>= 1) {
                sA += __shfl_xor_sync(0xffffffffu, sA, o);
                sB += __shfl_xor_sync(0xffffffffu, sB, o);
            }
            sA = aval ? sA * SCALE : -INFINITY;
            sB = bval ? sB * SCALE : -INFINITY;
            float mn   = fmaxf(m, fmaxf(sA, sB));
            float corr = __expf(m - mn);
            float pA   = __expf(sA - mn);
            float pB   = __expf(sB - mn);
            acc.x = acc.x * corr + pA * vA.x + pB * vB.x;
            acc.y = acc.y * corr + pA * vA.y + pB * vB.y;
            acc.z = acc.z * corr + pA * vA.z + pB * vB.z;
            acc.w = acc.w * corr + pA * vA.w + pB * vB.w;
            l = l * corr + pA + pB;
            m = mn;
        }
    }

    wacc[wid][lane * 4 + 0] = acc.x;
    wacc[wid][lane * 4 + 1] = acc.y;
    wacc[wid][lane * 4 + 2] = acc.z;
    wacc[wid][lane * 4 + 3] = acc.w;
    if (lane == 0) { wm[wid] = m; wl[wid] = l; }
    __syncthreads();

    if (tid < HEAD_DIM) {
        float mb = -INFINITY;
#pragma unroll
        for (int w = 0; w < 8; w++) mb = fmaxf(mb, wm[w]);
        float lb = 0.f, od = 0.f;
        if (mb != -INFINITY) {
#pragma unroll
            for (int w = 0; w < 8; w++) {
                float e = __expf(wm[w] - mb);
                lb += wl[w] * e;
                od += wacc[w][tid] * e;
            }
        }
        int idx = h * KB + kb;
        g_pacc[idx * HEAD_DIM + tid] = od;
        if (tid == 0) { g_pm[idx] = mb; g_pl[idx] = lb; }
    }
}

// ---------------- K3: per-head reduce + head-sliced projection (R12) ------
// grid = NUM_HEADS * 32 = 512 blocks of 128 threads. Block (h, jg):
//   1) replicates head h's split-combine (reads are L2-resident)
//   2) computes y-rows [jg*64, jg*64+64) partial dots over head h's 128 dims
//   3) atomicAdd into y (zeroed by qkv).
__global__ __launch_bounds__(128) void proj_head_kernel(
        const float* __restrict__ Wo, float* __restrict__ y) {
    int bid = blockIdx.x;
    int h   = bid >> 5;
    int jg  = bid & 31;
    int tid = threadIdx.x, warp = tid >> 5, lane = tid & 31;

    __shared__ float attn_sh[HEAD_DIM];
    __shared__ float red[HEAD_DIM];

    // ---- replicated per-head split combine (includes new-key term) ----
    red[tid] = g_q[h * HEAD_DIM + tid] * g_k[h * HEAD_DIM + tid];
    __syncthreads();
    for (int s = 64; s; s >>= 1) {
        if (tid < s) red[tid] += red[tid + s];
        __syncthreads();
    }
    float s_new = red[0] * SCALE;             // new key always valid

    float mg = s_new;
#pragma unroll 8
    for (int sp = 0; sp < KB; sp++) mg = fmaxf(mg, g_pm[h * KB + sp]);
    float en  = __expf(s_new - mg);
    float num = en * g_v[h * HEAD_DIM + tid];
    float den = en;
#pragma unroll 8
    for (int sp = 0; sp < KB; sp++) {
        float e = __expf(g_pm[h * KB + sp] - mg);
        num += e * g_pacc[(h * KB + sp) * HEAD_DIM + tid];
        den += e * g_pl[h * KB + sp];
    }
    attn_sh[tid] = num / den;
    __syncthreads();

    // ---- projection slice: 64 rows, 128 dims (512B coalesced per row) ----
    float4 a = ((const float4*)attn_sh)[lane];
    int rbase = jg * 64 + warp * 16;          // 16 rows per warp
    const float* wbase = Wo + (size_t)h * HEAD_DIM;

#pragma unroll
    for (int rr = 0; rr < 16; rr += 4) {
        float4 w[4];
#pragma unroll
        for (int u = 0; u < 4; u++)
            w[u] = __ldcs((const float4*)(wbase + (size_t)(rbase + rr + u) * D_MODEL) + lane);
        float s0 = w[0].x * a.x + w[0].y * a.y + w[0].z * a.z + w[0].w * a.w;
        float s1 = w[1].x * a.x + w[1].y * a.y + w[1].z * a.z + w[1].w * a.w;
        float s2 = w[2].x * a.x + w[2].y * a.y + w[2].z * a.z + w[2].w * a.w;
        float s3 = w[3].x * a.x + w[3].y * a.y + w[3].z * a.z + w[3].w * a.w;
#pragma unroll
        for (int o = 16; o; o >>= 1) {
            s0 += __shfl_xor_sync(0xffffffffu, s0, o);
            s1 += __shfl_xor_sync(0xffffffffu, s1, o);
            s2 += __shfl_xor_sync(0xffffffffu, s2, o);
            s3 += __shfl_xor_sync(0xffffffffu, s3, o);
        }
        if (lane == 0) {
            atomicAdd(y + rbase + rr + 0, s0);
            atomicAdd(y + rbase + rr + 1, s1);
            atomicAdd(y + rbase + rr + 2, s2);
            atomicAdd(y + rbase + rr + 3, s3);
        }
    }
}

// ---------------- launch ---------------------------------------------------
extern "C" void kernel_launch(void* const* d_in, const int* in_sizes, int n_in,
                              void* d_out, int out_size) {
    const float* x  = (const float*)d_in[0];
    const float* Wq = (const float*)d_in[1];
    const float* Wk = (const float*)d_in[2];
    const float* Wv = (const float*)d_in[3];
    const float* Wo = (const float*)d_in[4];
    const float* pk = (const float*)d_in[5];
    const float* pv = (const float*)d_in[6];
    const int*   ci = (const int*)d_in[7];

    float* y  = (float*)d_out;
    float* ok = y + D_MODEL;
    float* ov = ok + (size_t)MAX_SEQ_LEN * D_MODEL;

    qkv_kernel<<<1536, 256>>>(x, Wq, Wk, Wv, y);
    fused_copy_attn_kernel<<<NUM_HEADS * KB, 256>>>(
        (const float4*)pk, (const float4*)pv,
        (float4*)ok, (float4*)ov, ci);
    proj_head_kernel<<<NUM_HEADS * 32, 128>>>(Wo, y);
}